// round 16
// baseline (speedup 1.0000x reference)
#include <cuda_runtime.h>
#include <cuda_fp16.h>
#include <cstdint>

#define EDIM 1024
#define BDIM 1024
#define G4   4096
#define MAXT 16
#define OUTD 34

#define BM 128
#define BN 256
#define BK 64
#define NCK (EDIM / BK)        // 16 k-chunks
#define NTHREADS 512
#define NCTAS 128

#define STAGEB 49152           // A16K + B32K
#define AHI 0
#define BHI 16384
#define SMEM_LSTM (1024 + 3 * STAGEB)   // bias + 3 stages = 148480

#define HSZ (BDIM * EDIM)

// out_proj GEMM tiling
#define ONB 64
#define OSTAGE 24576           // A16K + B8K
#define OAHI 0
#define OBHI 16384
#define SMEM_OP (3 * OSTAGE)   // 73728

// ----------------- device scratch -----------------
__device__ __half g_Ws_h[G4 * EDIM];      // fp16(Wih+Whh), permuted
__device__ __half g_Wh_h[G4 * EDIM];      // fp16(Whh), permuted (step 0)
__device__ float  g_bsum_p[G4];
// h sequence in fp16: slot 0 = initial h, slot t+1 = h after step t
__device__ __half g_hseq[(MAXT + 1) * HSZ];
__device__ float  g_c[HSZ];
__device__ __half g_Wo_h[ONB * EDIM];     // rows 34..63 stay zero
__device__ unsigned int g_bar;            // grid barrier (reset each launch)

// ----------------- helpers -----------------
__device__ __forceinline__ uint32_t smem_u32(const void* p) {
    uint32_t a;
    asm("{ .reg .u64 t; cvta.to.shared.u64 t, %1; cvt.u32.u64 %0, t; }" : "=r"(a) : "l"(p));
    return a;
}
__device__ __forceinline__ void cpa16(uint32_t dst, const void* src) {
    asm volatile("cp.async.cg.shared.global [%0], [%1], 16;" :: "r"(dst), "l"(src));
}
__device__ __forceinline__ void cpa_commit() {
    asm volatile("cp.async.commit_group;" ::: "memory");
}
__device__ __forceinline__ void ldsm4(uint32_t* r, uint32_t a) {
    asm volatile("ldmatrix.sync.aligned.m8n8.x4.shared.b16 {%0,%1,%2,%3}, [%4];"
                 : "=r"(r[0]), "=r"(r[1]), "=r"(r[2]), "=r"(r[3]) : "r"(a));
}
__device__ __forceinline__ void mma16816(float* d,
                                         const uint32_t* a,
                                         uint32_t b0, uint32_t b1) {
    asm volatile("mma.sync.aligned.m16n8k16.row.col.f32.f16.f16.f32 "
                 "{%0,%1,%2,%3}, {%4,%5,%6,%7}, {%8,%9}, {%0,%1,%2,%3};"
                 : "+f"(d[0]), "+f"(d[1]), "+f"(d[2]), "+f"(d[3])
                 : "r"(a[0]), "r"(a[1]), "r"(a[2]), "r"(a[3]), "r"(b0), "r"(b1));
}
__device__ __forceinline__ float fsig(float x) {
    float t = __expf(-x);
    return __fdividef(1.f, 1.f + t);
}
__device__ __forceinline__ float ftanh_(float x) {
    float t = __expf(-2.f * x);
    return __fdividef(1.f - t, 1.f + t);
}

// permutation: original W row r = g*1024 + e  ->  rp = (e>>6)*256 + g*64 + (e&63)

// ----------------- prep kernels -----------------
__global__ void prep_w(const float* __restrict__ Wih, const float* __restrict__ Whh) {
    int id = blockIdx.x * 256 + threadIdx.x;
    int r = id >> 8;
    int q = id & 255;
    float4 a = reinterpret_cast<const float4*>(Wih)[(size_t)r * 256 + q];
    float4 b = reinterpret_cast<const float4*>(Whh)[(size_t)r * 256 + q];
    int g = r >> 10, e = r & 1023;
    int rp = ((e >> 6) << 8) + (g << 6) + (e & 63);
    size_t o = (size_t)rp * 256 + q;

    ushort4 wh, ws;
    wh.x = __half_as_ushort(__float2half_rn(b.x));
    wh.y = __half_as_ushort(__float2half_rn(b.y));
    wh.z = __half_as_ushort(__float2half_rn(b.z));
    wh.w = __half_as_ushort(__float2half_rn(b.w));
    ws.x = __half_as_ushort(__float2half_rn(a.x + b.x));
    ws.y = __half_as_ushort(__float2half_rn(a.y + b.y));
    ws.z = __half_as_ushort(__float2half_rn(a.z + b.z));
    ws.w = __half_as_ushort(__float2half_rn(a.w + b.w));

    reinterpret_cast<ushort4*>(g_Wh_h)[o] = wh;
    reinterpret_cast<ushort4*>(g_Ws_h)[o] = ws;
}

__global__ void prep_state(const float* __restrict__ h0, const float* __restrict__ c0,
                           const float* __restrict__ bih, const float* __restrict__ bhh,
                           const float* __restrict__ Wo) {
    int id = blockIdx.x * 256 + threadIdx.x;
    if (id == 0) g_bar = 0u;
    float4 hv = reinterpret_cast<const float4*>(h0)[id];
    ushort4 hh;
    hh.x = __half_as_ushort(__float2half_rn(hv.x));
    hh.y = __half_as_ushort(__float2half_rn(hv.y));
    hh.z = __half_as_ushort(__float2half_rn(hv.z));
    hh.w = __half_as_ushort(__float2half_rn(hv.w));
    reinterpret_cast<ushort4*>(g_hseq)[id] = hh;   // slot 0
    reinterpret_cast<float4*>(g_c)[id] = reinterpret_cast<const float4*>(c0)[id];
    if (id < G4) {
        int g = id >> 10, e = id & 1023;
        int rp = ((e >> 6) << 8) + (g << 6) + (e & 63);
        g_bsum_p[rp] = bih[id] + bhh[id];
    }
    if (id < OUTD * 256) {
        int r = id >> 8, q = id & 255;
        float4 wv = reinterpret_cast<const float4*>(Wo)[(size_t)r * 256 + q];
        ushort4 wh;
        wh.x = __half_as_ushort(__float2half_rn(wv.x));
        wh.y = __half_as_ushort(__float2half_rn(wv.y));
        wh.z = __half_as_ushort(__float2half_rn(wv.z));
        wh.w = __half_as_ushort(__float2half_rn(wv.w));
        reinterpret_cast<ushort4*>(g_Wo_h)[(size_t)r * 256 + q] = wh;
    }
}

// ----------------- persistent fused GEMM + LSTM (all T steps, grid barrier) ---
__global__ __launch_bounds__(NTHREADS, 1)
void lstm_persist(int T) {
    extern __shared__ char smem[];
    float* bias_sm = reinterpret_cast<float*>(smem);
    const uint32_t sbase = smem_u32(smem) + 1024;
    const int tid = threadIdx.x;
    const int lane = tid & 31;
    const int w = tid >> 5;
    const int wm = w & 3;
    const int we = w >> 2;
    const int nb = blockIdx.x;
    const int mb = blockIdx.y;
    const int m0 = mb * BM, n0 = nb * BN;

    if (tid < BN) bias_sm[tid] = g_bsum_p[n0 + tid];
    __syncthreads();

    const int lrow = tid >> 3;
    const int lq = tid & 7;
    const int arl = (lane & 7) + ((lane >> 3) & 1) * 8;
    const int adq = lane >> 4;
    const int bn = (lane & 7) + ((lane >> 4) << 3);
    const int bdq = (lane >> 3) & 1;
    const int mbase = m0 + wm * 32 + (lane >> 2);
    const int cp2 = (lane & 3) * 2;

#define LOAD_STAGE(s, kc)                                                          \
    {                                                                              \
        uint32_t sb = sbase + (s) * STAGEB;                                        \
        size_t gc = (size_t)(kc) * 64 + lq * 8;                                    \
        _Pragma("unroll")                                                          \
        for (int i = 0; i < 2; ++i) {                                              \
            int row = lrow + i * 64;                                               \
            uint32_t sf = (uint32_t)row * 128 + (((lq ^ (row & 7)) << 4));         \
            cpa16(sb + AHI + sf, hin + (size_t)(m0 + row) * EDIM + gc);            \
        }                                                                          \
        _Pragma("unroll")                                                          \
        for (int i = 0; i < 4; ++i) {                                              \
            int row = lrow + i * 64;                                               \
            uint32_t sf = (uint32_t)row * 128 + (((lq ^ (row & 7)) << 4));         \
            cpa16(sb + BHI + sf, Bh + (size_t)(n0 + row) * EDIM + gc);             \
        }                                                                          \
        cpa_commit();                                                              \
    }

    for (int t = 0; t < T; ++t) {
        const __half* hin = g_hseq + (size_t)t * HSZ;
        __half* hout = g_hseq + (size_t)(t + 1) * HSZ;
        const __half* Bh = t ? g_Ws_h : g_Wh_h;

        float acc[2][4][2][4];
#pragma unroll
        for (int i = 0; i < 2; ++i)
#pragma unroll
            for (int j = 0; j < 4; ++j)
#pragma unroll
                for (int s = 0; s < 2; ++s)
#pragma unroll
                    for (int k = 0; k < 4; ++k) acc[i][j][s][k] = 0.f;

        // prologue: chunks 0 and 1 in flight
        LOAD_STAGE(0, 0)
        LOAD_STAGE(1, 1)

        for (int kc = 0; kc < NCK; ++kc) {
            // chunk kc resident when at most 1 newer group (kc+1) remains in flight
            if (kc == NCK - 1)
                asm volatile("cp.async.wait_group 0;" ::: "memory");
            else
                asm volatile("cp.async.wait_group 1;" ::: "memory");
            __syncthreads();   // all warps done with stage (kc-1)%3 (compute kc-1)
            if (kc + 2 < NCK) {
                LOAD_STAGE((kc + 2) % 3, kc + 2)   // into freed stage (kc-1)%3
            }

            uint32_t sb = sbase + (kc % 3) * STAGEB;
#pragma unroll
            for (int k16 = 0; k16 < 4; ++k16) {
                int qa = k16 * 2 + adq;
                int qb = k16 * 2 + bdq;
                uint32_t aoffs[2], boffs[4];
#pragma unroll
                for (int mt = 0; mt < 2; ++mt) {
                    int ar = wm * 32 + mt * 16 + arl;
                    aoffs[mt] = (uint32_t)ar * 128 + ((qa ^ (ar & 7)) << 4);
                }
#pragma unroll
                for (int g = 0; g < 4; ++g) {
                    int br = g * 64 + we * 16 + bn;
                    boffs[g] = (uint32_t)br * 128 + ((qb ^ (br & 7)) << 4);
                }
                uint32_t ah[2][4], bf[4][4];
#pragma unroll
                for (int mt = 0; mt < 2; ++mt) ldsm4(ah[mt], sb + AHI + aoffs[mt]);
#pragma unroll
                for (int g = 0; g < 4; ++g) ldsm4(bf[g], sb + BHI + boffs[g]);
#pragma unroll
                for (int mt = 0; mt < 2; ++mt)
#pragma unroll
                    for (int g = 0; g < 4; ++g) {
                        mma16816(acc[mt][g][0], ah[mt], bf[g][0], bf[g][1]);
                        mma16816(acc[mt][g][1], ah[mt], bf[g][2], bf[g][3]);
                    }
            }
        }

        // ---- fused epilogue ----
#pragma unroll
        for (int mt = 0; mt < 2; ++mt) {
#pragma unroll
            for (int rr = 0; rr < 2; ++rr) {
                int m = mbase + mt * 16 + rr * 8;
#pragma unroll
                for (int sub = 0; sub < 2; ++sub) {
                    int el = we * 16 + sub * 8 + cp2;
                    float xi0 = acc[mt][0][sub][rr*2+0] + bias_sm[el];
                    float xi1 = acc[mt][0][sub][rr*2+1] + bias_sm[el + 1];
                    float xf0 = acc[mt][1][sub][rr*2+0] + bias_sm[64 + el];
                    float xf1 = acc[mt][1][sub][rr*2+1] + bias_sm[64 + el + 1];
                    float xg0 = acc[mt][2][sub][rr*2+0] + bias_sm[128 + el];
                    float xg1 = acc[mt][2][sub][rr*2+1] + bias_sm[128 + el + 1];
                    float xo0 = acc[mt][3][sub][rr*2+0] + bias_sm[192 + el];
                    float xo1 = acc[mt][3][sub][rr*2+1] + bias_sm[192 + el + 1];
                    size_t off = (size_t)m * EDIM + nb * 64 + el;
                    float2 cold = *reinterpret_cast<const float2*>(g_c + off);
                    float cn0 = fsig(xf0) * cold.x + fsig(xi0) * ftanh_(xg0);
                    float cn1 = fsig(xf1) * cold.y + fsig(xi1) * ftanh_(xg1);
                    float hn0 = fsig(xo0) * ftanh_(cn0);
                    float hn1 = fsig(xo1) * ftanh_(cn1);
                    *reinterpret_cast<float2*>(g_c + off) = make_float2(cn0, cn1);
                    uint32_t hp = (uint32_t)__half_as_ushort(__float2half_rn(hn0)) |
                                  ((uint32_t)__half_as_ushort(__float2half_rn(hn1)) << 16);
                    *reinterpret_cast<uint32_t*>(reinterpret_cast<unsigned short*>(hout) + off) = hp;
                }
            }
        }

        if (t + 1 < T) {
            __threadfence();
            __syncthreads();
            if (tid == 0) {
                unsigned tgt = (unsigned)(t + 1) * (unsigned)NCTAS;
                atomicAdd(&g_bar, 1u);
                while (atomicAdd(&g_bar, 0u) < tgt) __nanosleep(64);
            }
            __syncthreads();
        }
    }
#undef LOAD_STAGE
}

// ----------------- output projection: fp16 1-pass tensor-core GEMM -----------
__global__ __launch_bounds__(256, 1)
void out_proj_mma(const float* __restrict__ bo, float* __restrict__ out, int T) {
    extern __shared__ char smem[];
    const uint32_t sbase = smem_u32(smem);
    const int tid = threadIdx.x;
    const int lane = tid & 31;
    const int w = tid >> 5;        // 0..7
    const int wm = w & 3;
    const int wn = w >> 2;         // 0..1
    const int gr0 = blockIdx.x * 128;      // t*1024 + b
    const int t = gr0 >> 10;
    const int b0 = gr0 & 1023;

    const __half* Ah = g_hseq + (size_t)(t + 1) * HSZ + (size_t)b0 * EDIM;

    const int lrow = tid >> 3;
    const int lq = tid & 7;

#define OLOAD(s, kc)                                                               \
    {                                                                              \
        uint32_t sb = sbase + (s) * OSTAGE;                                        \
        size_t gc = (size_t)(kc) * 64 + lq * 8;                                    \
        _Pragma("unroll")                                                          \
        for (int i = 0; i < 4; ++i) {                                              \
            int row = lrow + i * 32;                                               \
            uint32_t sf = (uint32_t)row * 128 + (((lq ^ (row & 7)) << 4));         \
            cpa16(sb + OAHI + sf, Ah + (size_t)row * EDIM + gc);                   \
        }                                                                          \
        _Pragma("unroll")                                                          \
        for (int i = 0; i < 2; ++i) {                                              \
            int row = lrow + i * 32;                                               \
            uint32_t sf = (uint32_t)row * 128 + (((lq ^ (row & 7)) << 4));         \
            cpa16(sb + OBHI + sf, g_Wo_h + (size_t)row * EDIM + gc);               \
        }                                                                          \
        cpa_commit();                                                              \
    }

    float acc[2][2][2][4];
#pragma unroll
    for (int i = 0; i < 2; ++i)
#pragma unroll
        for (int j = 0; j < 2; ++j)
#pragma unroll
            for (int s = 0; s < 2; ++s)
#pragma unroll
                for (int k = 0; k < 4; ++k) acc[i][j][s][k] = 0.f;

    const int arl = (lane & 7) + ((lane >> 3) & 1) * 8;
    const int adq = lane >> 4;
    const int bn = (lane & 7) + ((lane >> 4) << 3);
    const int bdq = (lane >> 3) & 1;

    OLOAD(0, 0)
    OLOAD(1, 1)

    for (int kc = 0; kc < NCK; ++kc) {
        if (kc == NCK - 1)
            asm volatile("cp.async.wait_group 0;" ::: "memory");
        else
            asm volatile("cp.async.wait_group 1;" ::: "memory");
        __syncthreads();
        if (kc + 2 < NCK) {
            OLOAD((kc + 2) % 3, kc + 2)
        }
        uint32_t sb = sbase + (kc % 3) * OSTAGE;
#pragma unroll
        for (int k16 = 0; k16 < 4; ++k16) {
            int qa = k16 * 2 + adq;
            int qb = k16 * 2 + bdq;
            uint32_t aoffs[2], boffs[2];
#pragma unroll
            for (int mt = 0; mt < 2; ++mt) {
                int ar = wm * 32 + mt * 16 + arl;
                aoffs[mt] = (uint32_t)ar * 128 + ((qa ^ (ar & 7)) << 4);
            }
#pragma unroll
            for (int nt = 0; nt < 2; ++nt) {
                int br = wn * 32 + nt * 16 + bn;
                boffs[nt] = (uint32_t)br * 128 + ((qb ^ (br & 7)) << 4);
            }
            uint32_t ah[2][4], bf[2][4];
#pragma unroll
            for (int mt = 0; mt < 2; ++mt) ldsm4(ah[mt], sb + OAHI + aoffs[mt]);
#pragma unroll
            for (int nt = 0; nt < 2; ++nt) ldsm4(bf[nt], sb + OBHI + boffs[nt]);
#pragma unroll
            for (int mt = 0; mt < 2; ++mt)
#pragma unroll
                for (int nt = 0; nt < 2; ++nt) {
                    mma16816(acc[mt][nt][0], ah[mt], bf[nt][0], bf[nt][1]);
                    mma16816(acc[mt][nt][1], ah[mt], bf[nt][2], bf[nt][3]);
                }
        }
    }
#undef OLOAD

    const int rbase = wm * 32 + (lane >> 2);
    const int cp2 = (lane & 3) * 2;
#pragma unroll
    for (int mt = 0; mt < 2; ++mt) {
#pragma unroll
        for (int rr = 0; rr < 2; ++rr) {
            int b = b0 + rbase + mt * 16 + rr * 8;
            size_t ob = ((size_t)b * T + t) * OUTD;
#pragma unroll
            for (int nt = 0; nt < 2; ++nt) {
#pragma unroll
                for (int sub = 0; sub < 2; ++sub) {
                    int o = wn * 32 + nt * 16 + sub * 8 + cp2;
                    if (o < OUTD)
                        out[ob + o] = acc[mt][nt][sub][rr*2+0] + __ldg(bo + o);
                    if (o + 1 < OUTD)
                        out[ob + o + 1] = acc[mt][nt][sub][rr*2+1] + __ldg(bo + o + 1);
                }
            }
        }
    }
}

// ----------------- launch -----------------
extern "C" void kernel_launch(void* const* d_in, const int* in_sizes, int n_in,
                              void* d_out, int out_size) {
    const float* h     = (const float*)d_in[0];
    const float* c     = (const float*)d_in[1];
    const float* W_ih  = (const float*)d_in[2];
    const float* W_hh  = (const float*)d_in[3];
    const float* b_ih  = (const float*)d_in[4];
    const float* b_hh  = (const float*)d_in[5];
    const float* W_out = (const float*)d_in[6];
    const float* b_out = (const float*)d_in[7];
    float* out = (float*)d_out;

    int T = out_size / (BDIM * OUTD);
    if (T < 1) T = 1;
    if (T > MAXT) T = MAXT;

    cudaFuncSetAttribute(lstm_persist, cudaFuncAttributeMaxDynamicSharedMemorySize, SMEM_LSTM);
    cudaFuncSetAttribute(out_proj_mma, cudaFuncAttributeMaxDynamicSharedMemorySize, SMEM_OP);

    prep_w<<<G4, 256>>>(W_ih, W_hh);
    prep_state<<<(BDIM * EDIM / 4) / 256, 256>>>(h, c, b_ih, b_hh, W_out);

    dim3 grid(G4 / BN, BDIM / BM);   // (16, 8) = 128 CTAs = 1 per SM, all resident
    lstm_persist<<<grid, NTHREADS, SMEM_LSTM>>>(T);

    out_proj_mma<<<8 * T, 256, SMEM_OP>>>(b_out, out, T);
}

// round 17
// speedup vs baseline: 1.2383x; 1.2383x over previous
#include <cuda_runtime.h>
#include <cuda_fp16.h>
#include <cstdint>

#define EDIM 1024
#define BDIM 1024
#define G4   4096
#define MAXT 16
#define OUTD 34

#define BM 128
#define BN 256
#define BK 64
#define NCK (EDIM / BK)        // 16 k-chunks
#define NTHREADS 512
#define NCTAS 128

#define STAGEB 49152           // A16K + B32K
#define AHI 0
#define BHI 16384
#define SMEM_LSTM (1024 + 2 * STAGEB)   // bias + 2 stages = 99328

#define HSZ (BDIM * EDIM)

// fused out_proj tiling (uses same smem region)
#define ONB 64
#define OSTAGE 24576           // A16K + B8K
#define OAHI 0
#define OBHI 16384

// ----------------- device scratch -----------------
__device__ __half g_Ws_h[G4 * EDIM];      // fp16(Wih+Whh), permuted
__device__ __half g_Wh_h[G4 * EDIM];      // fp16(Whh), permuted (step 0)
__device__ float  g_bsum_p[G4];
// h sequence in fp16: slot 0 = initial h, slot t+1 = h after step t
__device__ __half g_hseq[(MAXT + 1) * HSZ];
__device__ float  g_c[HSZ];
__device__ __half g_Wo_h[ONB * EDIM];     // rows 34..63 stay zero
__device__ unsigned int g_bar;            // grid barrier (reset each launch)

// ----------------- helpers -----------------
__device__ __forceinline__ uint32_t smem_u32(const void* p) {
    uint32_t a;
    asm("{ .reg .u64 t; cvta.to.shared.u64 t, %1; cvt.u32.u64 %0, t; }" : "=r"(a) : "l"(p));
    return a;
}
__device__ __forceinline__ void cpa16(uint32_t dst, const void* src) {
    asm volatile("cp.async.cg.shared.global [%0], [%1], 16;" :: "r"(dst), "l"(src));
}
__device__ __forceinline__ void cpa_commit() {
    asm volatile("cp.async.commit_group;" ::: "memory");
}
__device__ __forceinline__ void ldsm4(uint32_t* r, uint32_t a) {
    asm volatile("ldmatrix.sync.aligned.m8n8.x4.shared.b16 {%0,%1,%2,%3}, [%4];"
                 : "=r"(r[0]), "=r"(r[1]), "=r"(r[2]), "=r"(r[3]) : "r"(a));
}
__device__ __forceinline__ void mma16816(float* d,
                                         const uint32_t* a,
                                         uint32_t b0, uint32_t b1) {
    asm volatile("mma.sync.aligned.m16n8k16.row.col.f32.f16.f16.f32 "
                 "{%0,%1,%2,%3}, {%4,%5,%6,%7}, {%8,%9}, {%0,%1,%2,%3};"
                 : "+f"(d[0]), "+f"(d[1]), "+f"(d[2]), "+f"(d[3])
                 : "r"(a[0]), "r"(a[1]), "r"(a[2]), "r"(a[3]), "r"(b0), "r"(b1));
}
__device__ __forceinline__ float fsig(float x) {
    float t = __expf(-x);
    return __fdividef(1.f, 1.f + t);
}
__device__ __forceinline__ float ftanh_(float x) {
    float t = __expf(-2.f * x);
    return __fdividef(1.f - t, 1.f + t);
}

// permutation: original W row r = g*1024 + e  ->  rp = (e>>6)*256 + g*64 + (e&63)

// ----------------- merged prep kernel -----------------
__global__ void prep_all(const float* __restrict__ Wih, const float* __restrict__ Whh,
                         const float* __restrict__ h0, const float* __restrict__ c0,
                         const float* __restrict__ bih, const float* __restrict__ bhh,
                         const float* __restrict__ Wo) {
    int id = blockIdx.x * 256 + threadIdx.x;   // 0 .. 1,048,575
    if (id == 0) g_bar = 0u;

    // --- weights: one float4 of Wih/Whh per thread ---
    {
        int r = id >> 8;
        int q = id & 255;
        float4 a = reinterpret_cast<const float4*>(Wih)[(size_t)r * 256 + q];
        float4 b = reinterpret_cast<const float4*>(Whh)[(size_t)r * 256 + q];
        int g = r >> 10, e = r & 1023;
        int rp = ((e >> 6) << 8) + (g << 6) + (e & 63);
        size_t o = (size_t)rp * 256 + q;
        ushort4 wh, ws;
        wh.x = __half_as_ushort(__float2half_rn(b.x));
        wh.y = __half_as_ushort(__float2half_rn(b.y));
        wh.z = __half_as_ushort(__float2half_rn(b.z));
        wh.w = __half_as_ushort(__float2half_rn(b.w));
        ws.x = __half_as_ushort(__float2half_rn(a.x + b.x));
        ws.y = __half_as_ushort(__float2half_rn(a.y + b.y));
        ws.z = __half_as_ushort(__float2half_rn(a.z + b.z));
        ws.w = __half_as_ushort(__float2half_rn(a.w + b.w));
        reinterpret_cast<ushort4*>(g_Wh_h)[o] = wh;
        reinterpret_cast<ushort4*>(g_Ws_h)[o] = ws;
    }

    if (id < (BDIM * EDIM) / 4) {          // h0 / c0
        float4 hv = reinterpret_cast<const float4*>(h0)[id];
        ushort4 hh;
        hh.x = __half_as_ushort(__float2half_rn(hv.x));
        hh.y = __half_as_ushort(__float2half_rn(hv.y));
        hh.z = __half_as_ushort(__float2half_rn(hv.z));
        hh.w = __half_as_ushort(__float2half_rn(hv.w));
        reinterpret_cast<ushort4*>(g_hseq)[id] = hh;   // slot 0
        reinterpret_cast<float4*>(g_c)[id] = reinterpret_cast<const float4*>(c0)[id];
    }
    if (id < G4) {                          // permuted bias sum
        int g = id >> 10, e = id & 1023;
        int rp = ((e >> 6) << 8) + (g << 6) + (e & 63);
        g_bsum_p[rp] = bih[id] + bhh[id];
    }
    if (id < OUTD * 256) {                  // W_out -> fp16
        int r = id >> 8, q = id & 255;
        float4 wv = reinterpret_cast<const float4*>(Wo)[(size_t)r * 256 + q];
        ushort4 wh;
        wh.x = __half_as_ushort(__float2half_rn(wv.x));
        wh.y = __half_as_ushort(__float2half_rn(wv.y));
        wh.z = __half_as_ushort(__float2half_rn(wv.z));
        wh.w = __half_as_ushort(__float2half_rn(wv.w));
        reinterpret_cast<ushort4*>(g_Wo_h)[(size_t)r * 256 + q] = wh;
    }
}

// ----------------- persistent: T LSTM steps + fused output projection --------
__global__ __launch_bounds__(NTHREADS, 1)
void lstm_persist(int T, const float* __restrict__ bo, float* __restrict__ out) {
    extern __shared__ char smem[];
    float* bias_sm = reinterpret_cast<float*>(smem);
    const uint32_t sbase = smem_u32(smem) + 1024;
    const int tid = threadIdx.x;
    const int lane = tid & 31;
    const int w = tid >> 5;
    const int wm = w & 3;
    const int we = w >> 2;
    const int nb = blockIdx.x;
    const int mb = blockIdx.y;
    const int m0 = mb * BM, n0 = nb * BN;

    if (tid < BN) bias_sm[tid] = g_bsum_p[n0 + tid];
    __syncthreads();

    const int lrow = tid >> 3;
    const int lq = tid & 7;
    const int arl = (lane & 7) + ((lane >> 3) & 1) * 8;
    const int adq = lane >> 4;
    const int bn = (lane & 7) + ((lane >> 4) << 3);
    const int bdq = (lane >> 3) & 1;
    const int mbase = m0 + wm * 32 + (lane >> 2);
    const int cp2 = (lane & 3) * 2;

#define LOAD_STAGE(s, kc)                                                          \
    {                                                                              \
        uint32_t sb = sbase + (s) * STAGEB;                                        \
        size_t gc = (size_t)(kc) * 64 + lq * 8;                                    \
        _Pragma("unroll")                                                          \
        for (int i = 0; i < 2; ++i) {                                              \
            int row = lrow + i * 64;                                               \
            uint32_t sf = (uint32_t)row * 128 + (((lq ^ (row & 7)) << 4));         \
            cpa16(sb + AHI + sf, hin + (size_t)(m0 + row) * EDIM + gc);            \
        }                                                                          \
        _Pragma("unroll")                                                          \
        for (int i = 0; i < 4; ++i) {                                              \
            int row = lrow + i * 64;                                               \
            uint32_t sf = (uint32_t)row * 128 + (((lq ^ (row & 7)) << 4));         \
            cpa16(sb + BHI + sf, Bh + (size_t)(n0 + row) * EDIM + gc);             \
        }                                                                          \
        cpa_commit();                                                              \
    }

    for (int t = 0; t < T; ++t) {
        const __half* hin = g_hseq + (size_t)t * HSZ;
        __half* hout = g_hseq + (size_t)(t + 1) * HSZ;
        const __half* Bh = t ? g_Ws_h : g_Wh_h;

        float acc[2][4][2][4];
#pragma unroll
        for (int i = 0; i < 2; ++i)
#pragma unroll
            for (int j = 0; j < 4; ++j)
#pragma unroll
                for (int s = 0; s < 2; ++s)
#pragma unroll
                    for (int k = 0; k < 4; ++k) acc[i][j][s][k] = 0.f;

        LOAD_STAGE(0, 0)

        for (int kc = 0; kc < NCK; ++kc) {
            asm volatile("cp.async.wait_group 0;" ::: "memory");
            __syncthreads();
            if (kc + 1 < NCK) {
                LOAD_STAGE((kc + 1) & 1, kc + 1)
            }
            uint32_t sb = sbase + (kc & 1) * STAGEB;
#pragma unroll
            for (int k16 = 0; k16 < 4; ++k16) {
                int qa = k16 * 2 + adq;
                int qb = k16 * 2 + bdq;
                uint32_t aoffs[2], boffs[4];
#pragma unroll
                for (int mt = 0; mt < 2; ++mt) {
                    int ar = wm * 32 + mt * 16 + arl;
                    aoffs[mt] = (uint32_t)ar * 128 + ((qa ^ (ar & 7)) << 4);
                }
#pragma unroll
                for (int g = 0; g < 4; ++g) {
                    int br = g * 64 + we * 16 + bn;
                    boffs[g] = (uint32_t)br * 128 + ((qb ^ (br & 7)) << 4);
                }
                uint32_t ah[2][4], bf[4][4];
#pragma unroll
                for (int mt = 0; mt < 2; ++mt) ldsm4(ah[mt], sb + AHI + aoffs[mt]);
#pragma unroll
                for (int g = 0; g < 4; ++g) ldsm4(bf[g], sb + BHI + boffs[g]);
#pragma unroll
                for (int mt = 0; mt < 2; ++mt)
#pragma unroll
                    for (int g = 0; g < 4; ++g) {
                        mma16816(acc[mt][g][0], ah[mt], bf[g][0], bf[g][1]);
                        mma16816(acc[mt][g][1], ah[mt], bf[g][2], bf[g][3]);
                    }
            }
        }

        // ---- fused epilogue ----
#pragma unroll
        for (int mt = 0; mt < 2; ++mt) {
#pragma unroll
            for (int rr = 0; rr < 2; ++rr) {
                int m = mbase + mt * 16 + rr * 8;
#pragma unroll
                for (int sub = 0; sub < 2; ++sub) {
                    int el = we * 16 + sub * 8 + cp2;
                    float xi0 = acc[mt][0][sub][rr*2+0] + bias_sm[el];
                    float xi1 = acc[mt][0][sub][rr*2+1] + bias_sm[el + 1];
                    float xf0 = acc[mt][1][sub][rr*2+0] + bias_sm[64 + el];
                    float xf1 = acc[mt][1][sub][rr*2+1] + bias_sm[64 + el + 1];
                    float xg0 = acc[mt][2][sub][rr*2+0] + bias_sm[128 + el];
                    float xg1 = acc[mt][2][sub][rr*2+1] + bias_sm[128 + el + 1];
                    float xo0 = acc[mt][3][sub][rr*2+0] + bias_sm[192 + el];
                    float xo1 = acc[mt][3][sub][rr*2+1] + bias_sm[192 + el + 1];
                    size_t off = (size_t)m * EDIM + nb * 64 + el;
                    float2 cold = *reinterpret_cast<const float2*>(g_c + off);
                    float cn0 = fsig(xf0) * cold.x + fsig(xi0) * ftanh_(xg0);
                    float cn1 = fsig(xf1) * cold.y + fsig(xi1) * ftanh_(xg1);
                    float hn0 = fsig(xo0) * ftanh_(cn0);
                    float hn1 = fsig(xo1) * ftanh_(cn1);
                    *reinterpret_cast<float2*>(g_c + off) = make_float2(cn0, cn1);
                    uint32_t hp = (uint32_t)__half_as_ushort(__float2half_rn(hn0)) |
                                  ((uint32_t)__half_as_ushort(__float2half_rn(hn1)) << 16);
                    *reinterpret_cast<uint32_t*>(reinterpret_cast<unsigned short*>(hout) + off) = hp;
                }
            }
        }

        // inter-step grid barrier
        __threadfence();
        __syncthreads();
        if (tid == 0) {
            unsigned tgt = (unsigned)(t + 1) * (unsigned)NCTAS;
            atomicAdd(&g_bar, 1u);
            while (atomicAdd(&g_bar, 0u) < tgt) __nanosleep(64);
        }
        __syncthreads();
    }
#undef LOAD_STAGE

    // =============== fused output projection (after final barrier) ===========
    // CTAs 0..8*T-1 each compute one [128 batch rows x 64 o-cols] tile.
    const int lin = blockIdx.y * 16 + blockIdx.x;
    if (lin >= 8 * T) return;
    const int tt = lin >> 3;
    const int pb0 = (lin & 7) * 128;
    const __half* Ah = g_hseq + (size_t)(tt + 1) * HSZ + (size_t)pb0 * EDIM;

    // 16 warps: m16 group (w&7), n32 group (w>>3)
    const int pwm = w & 7;
    const int pwn = w >> 3;

#define PLOAD(s, kc)                                                               \
    {                                                                              \
        uint32_t sb = sbase + (s) * OSTAGE;                                        \
        size_t gc = (size_t)(kc) * 64 + lq * 8;                                    \
        _Pragma("unroll")                                                          \
        for (int i = 0; i < 2; ++i) {                                              \
            int row = lrow + i * 64;                                               \
            uint32_t sf = (uint32_t)row * 128 + (((lq ^ (row & 7)) << 4));         \
            cpa16(sb + OAHI + sf, Ah + (size_t)row * EDIM + gc);                   \
        }                                                                          \
        {                                                                          \
            int row = lrow;                                                        \
            uint32_t sf = (uint32_t)row * 128 + (((lq ^ (row & 7)) << 4));         \
            cpa16(sb + OBHI + sf, g_Wo_h + (size_t)row * EDIM + gc);               \
        }                                                                          \
        cpa_commit();                                                              \
    }

    float pacc[2][2][4];   // [nt][sub][4]
#pragma unroll
    for (int i = 0; i < 2; ++i)
#pragma unroll
        for (int j = 0; j < 2; ++j)
#pragma unroll
            for (int k = 0; k < 4; ++k) pacc[i][j][k] = 0.f;

    PLOAD(0, 0)

    for (int kc = 0; kc < NCK; ++kc) {
        asm volatile("cp.async.wait_group 0;" ::: "memory");
        __syncthreads();
        if (kc + 1 < NCK) {
            PLOAD((kc + 1) & 1, kc + 1)
        }
        uint32_t sb = sbase + (kc & 1) * OSTAGE;
#pragma unroll
        for (int k16 = 0; k16 < 4; ++k16) {
            int qa = k16 * 2 + adq;
            int qb = k16 * 2 + bdq;
            int ar = pwm * 16 + arl;
            uint32_t aoff = (uint32_t)ar * 128 + ((qa ^ (ar & 7)) << 4);
            uint32_t boffs[2];
#pragma unroll
            for (int nt = 0; nt < 2; ++nt) {
                int br = pwn * 32 + nt * 16 + bn;
                boffs[nt] = (uint32_t)br * 128 + ((qb ^ (br & 7)) << 4);
            }
            uint32_t ah[4], bf[2][4];
            ldsm4(ah, sb + OAHI + aoff);
#pragma unroll
            for (int nt = 0; nt < 2; ++nt) ldsm4(bf[nt], sb + OBHI + boffs[nt]);
#pragma unroll
            for (int nt = 0; nt < 2; ++nt) {
                mma16816(pacc[nt][0], ah, bf[nt][0], bf[nt][1]);
                mma16816(pacc[nt][1], ah, bf[nt][2], bf[nt][3]);
            }
        }
    }
#undef PLOAD

    const int prow = pwm * 16 + (lane >> 2);
#pragma unroll
    for (int rr = 0; rr < 2; ++rr) {
        int b = pb0 + prow + rr * 8;
        size_t ob = ((size_t)b * T + tt) * OUTD;
#pragma unroll
        for (int nt = 0; nt < 2; ++nt) {
#pragma unroll
            for (int sub = 0; sub < 2; ++sub) {
                int o = pwn * 32 + nt * 16 + sub * 8 + cp2;
                if (o < OUTD)
                    out[ob + o] = pacc[nt][sub][rr*2+0] + __ldg(bo + o);
                if (o + 1 < OUTD)
                    out[ob + o + 1] = pacc[nt][sub][rr*2+1] + __ldg(bo + o + 1);
            }
        }
    }
}

// ----------------- launch -----------------
extern "C" void kernel_launch(void* const* d_in, const int* in_sizes, int n_in,
                              void* d_out, int out_size) {
    const float* h     = (const float*)d_in[0];
    const float* c     = (const float*)d_in[1];
    const float* W_ih  = (const float*)d_in[2];
    const float* W_hh  = (const float*)d_in[3];
    const float* b_ih  = (const float*)d_in[4];
    const float* b_hh  = (const float*)d_in[5];
    const float* W_out = (const float*)d_in[6];
    const float* b_out = (const float*)d_in[7];
    float* out = (float*)d_out;

    int T = out_size / (BDIM * OUTD);
    if (T < 1) T = 1;
    if (T > MAXT) T = MAXT;

    cudaFuncSetAttribute(lstm_persist, cudaFuncAttributeMaxDynamicSharedMemorySize, SMEM_LSTM);

    prep_all<<<G4, 256>>>(W_ih, W_hh, h, c, b_ih, b_hh, W_out);

    dim3 grid(G4 / BN, BDIM / BM);   // (16, 8) = 128 CTAs = 1 per SM, all resident
    lstm_persist<<<grid, NTHREADS, SMEM_LSTM>>>(T, b_out, out);
}